// round 6
// baseline (speedup 1.0000x reference)
#include <cuda_runtime.h>

// CCSDS-123 lossless predictor, [Z=224, Y=512, X=512].
// 8 rows per block, software-pipelined row loads, streaming stores.

#define ZB 224
#define YB 512
#define XB 512
#define ROWS 8

static constexpr size_t PLANE = (size_t)ZB * YB * XB;   // 58,720,256

__global__ __launch_bounds__(128) void ccsds123_kernel(
    const float* __restrict__ img, float* __restrict__ out)
{
    const int chunk = blockIdx.x;          // 224 * 64 chunks
    const int z  = chunk >> 6;             // / 64
    const int y0 = (chunk & 63) << 3;      // * ROWS
    const int tid = threadIdx.x;

    __shared__ float C[4][XB];   // rotating center-row buffers (C[(j)&3] = row y0+j)
    __shared__ float P[2][XB];   // rotating prev-band-row buffers

    const float4 zero4 = make_float4(0.f, 0.f, 0.f, 0.f);
    const float* base  = img + ((size_t)z * YB + y0) * XB;
    const float* pbase = base - (size_t)YB * XB;   // prev band (valid iff z > 0)

    // Prologue: north of first row into C[3] (= C[(-1)&3]); row y0; prev-band row y0.
    ((float4*)C[3])[tid] = (y0 > 0) ? ((const float4*)(base - XB))[tid] : zero4;
    ((float4*)C[0])[tid] = ((const float4*)base)[tid];
    if (z > 0) {
        ((float4*)P[0])[tid] = ((const float4*)pbase)[tid];
    } else {
        ((float4*)P[0])[tid] = zero4;
        ((float4*)P[1])[tid] = zero4;
    }

    const int x0 = tid * 4;

    for (int j = 0; j < ROWS; ++j) {
        __syncthreads();   // prefetch from iter j-1 (and prologue) now visible

        // Prefetch row j+1 (center + prev band) into buffers not read this iter.
        if (j + 1 < ROWS) {
            ((float4*)C[(j + 1) & 3])[tid] =
                ((const float4*)(base + (size_t)(j + 1) * XB))[tid];
            if (z > 0)
                ((float4*)P[(j + 1) & 1])[tid] =
                    ((const float4*)(pbase + (size_t)(j + 1) * XB))[tid];
        }

        const float* sc = C[j & 3];          // center row  s(z, y, :)
        const float* sn = C[(j + 3) & 3];    // north row   s(z, y-1, :)
        const float* sp = P[j & 1];          // prev band   s(z-1, y, :)
        const int y = y0 + j;

        float pr[4], rs[4], mp[4], rc[4];
#pragma unroll
        for (int i = 0; i < 4; ++i) {
            const int x = x0 + i;
            const float Cv  = sc[x];
            const float Wv  = (x > 0)      ? sc[x - 1] : 0.f;
            const float Nv  = sn[x];
            const float NWv = (x > 0)      ? sn[x - 1] : 0.f;
            const float NEv = (x < XB - 1) ? sn[x + 1] : 0.f;

            float sigma;
            if (y == 0)           sigma = (x == 0) ? 0.f : 4.f * Wv;   // top row
            else if (x == 0)      sigma = 2.f * (Nv + NEv);            // left col
            else if (x == XB - 1) sigma = Wv + NWv + 2.f * Nv;         // right col
            else                  sigma = Wv + NWv + Nv + NEv;         // interior

            const float spred = sigma * 0.25f;
            const float pb    = sp[x];

            float p = (z == 0) ? spred : 0.5f * (spred + pb);
            if (y == 0 && x == 0) p = (z == 0) ? 0.f : pb;             // origin

            const float r = Cv - p;                    // residual (== quantized)
            const float q = rintf(r);                  // matches jnp.round
            const float m = (q >= 0.f) ? (2.f * q) : (-2.f * q - 1.f); // zigzag
            const float rec = fminf(fmaxf(p + r, -32768.f), 32767.f);  // clip

            pr[i] = p; rs[i] = r; mp[i] = m; rc[i] = rec;
        }

        const size_t off = ((size_t)z * YB + y) * XB + (size_t)x0;
        const float4 v_p = make_float4(pr[0], pr[1], pr[2], pr[3]);
        const float4 v_r = make_float4(rs[0], rs[1], rs[2], rs[3]);
        const float4 v_m = make_float4(mp[0], mp[1], mp[2], mp[3]);
        const float4 v_c = make_float4(rc[0], rc[1], rc[2], rc[3]);

        __stcs((float4*)(out + off),             v_p);  // predictions
        __stcs((float4*)(out + off + PLANE),     v_r);  // residuals
        __stcs((float4*)(out + off + 2 * PLANE), v_r);  // quantized residuals
        __stcs((float4*)(out + off + 3 * PLANE), v_m);  // mapped indices
        __stcs((float4*)(out + off + 4 * PLANE), v_c);  // sample representatives
        __stcs((float4*)(out + off + 5 * PLANE), v_c);  // reconstructed
    }
}

extern "C" void kernel_launch(void* const* d_in, const int* in_sizes, int n_in,
                              void* d_out, int out_size)
{
    const float* img = (const float*)d_in[0];
    float* out = (float*)d_out;
    ccsds123_kernel<<<ZB * (YB / ROWS), 128>>>(img, out);
}

// round 9
// speedup vs baseline: 1.0567x; 1.0567x over previous
#include <cuda_runtime.h>

// CCSDS-123 lossless predictor, [Z=224, Y=512, X=512].
// 2 rows per 256-thread block (flat, one barrier), streaming stores.

#define ZB 224
#define YB 512
#define XB 512

static constexpr size_t PLANE = (size_t)ZB * YB * XB;   // 58,720,256

__global__ __launch_bounds__(256, 8) void ccsds123_kernel(
    const float* __restrict__ img, float* __restrict__ out)
{
    const int b   = blockIdx.x;          // 224 * 256 blocks
    const int z   = b >> 8;              // / 256
    const int y0  = (b & 255) << 1;      // row pair
    const int tid = threadIdx.x;

    __shared__ float SC[2 * XB];   // center rows y0, y0+1
    __shared__ float SN[XB];       // north row  y0-1
    __shared__ float SP[2 * XB];   // prev band rows y0, y0+1

    const float4 zero4 = make_float4(0.f, 0.f, 0.f, 0.f);
    const float* base  = img + ((size_t)z * YB + y0) * XB;
    const float* pbase = base - (size_t)YB * XB;     // valid iff z > 0

    // Stage: 256 float4s cover both center rows / both prev-band rows.
    ((float4*)SC)[tid] = ((const float4*)base)[tid];
    if (z > 0) {
        float4 pv;
        const float4* p4 = (const float4*)pbase + tid;
        pv.x = __ldcs((const float*)p4 + 0);
        pv.y = __ldcs((const float*)p4 + 1);
        pv.z = __ldcs((const float*)p4 + 2);
        pv.w = __ldcs((const float*)p4 + 3);
        ((float4*)SP)[tid] = pv;
    } else {
        ((float4*)SP)[tid] = zero4;
    }
    if (tid < 128)
        ((float4*)SN)[tid] = (y0 > 0) ? ((const float4*)(base - XB))[tid] : zero4;
    __syncthreads();

    const int half = tid >> 7;               // which of the two rows
    const int t    = tid & 127;
    const int x0   = t * 4;
    const int y    = y0 + half;

    const float* sc = SC + half * XB;        // center row s(z, y, :)
    const float* sn = half ? SC : SN;        // north row  s(z, y-1, :)
    const float* sp = SP + half * XB;        // prev band  s(z-1, y, :)

    float pr[4], rs[4], mp[4], rc[4];

#pragma unroll
    for (int i = 0; i < 4; ++i) {
        const int x = x0 + i;
        const float Cv  = sc[x];
        const float Wv  = (x > 0)      ? sc[x - 1] : 0.f;
        const float Nv  = sn[x];
        const float NWv = (x > 0)      ? sn[x - 1] : 0.f;
        const float NEv = (x < XB - 1) ? sn[x + 1] : 0.f;

        // neighbor-oriented local sum with edge cases
        float sigma;
        if (y == 0)           sigma = (x == 0) ? 0.f : 4.f * Wv;   // top row
        else if (x == 0)      sigma = 2.f * (Nv + NEv);            // left col
        else if (x == XB - 1) sigma = Wv + NWv + 2.f * Nv;         // right col
        else                  sigma = Wv + NWv + Nv + NEv;         // interior

        const float spred = sigma * 0.25f;
        const float pb    = sp[x];

        float p = (z == 0) ? spred : 0.5f * (spred + pb);
        if (y == 0 && x == 0) p = (z == 0) ? 0.f : pb;             // origin

        const float r = Cv - p;                    // residual (== quantized)
        const float q = rintf(r);                  // half-to-even, matches jnp.round
        const float m = (q >= 0.f) ? (2.f * q) : (-2.f * q - 1.f); // zigzag
        const float rec = fminf(fmaxf(p + r, -32768.f), 32767.f);  // clip

        pr[i] = p; rs[i] = r; mp[i] = m; rc[i] = rec;
    }

    const size_t off = ((size_t)z * YB + y) * XB + (size_t)x0;
    const float4 v_p = make_float4(pr[0], pr[1], pr[2], pr[3]);
    const float4 v_r = make_float4(rs[0], rs[1], rs[2], rs[3]);
    const float4 v_m = make_float4(mp[0], mp[1], mp[2], mp[3]);
    const float4 v_c = make_float4(rc[0], rc[1], rc[2], rc[3]);

    __stcs((float4*)(out + off),             v_p);  // predictions
    __stcs((float4*)(out + off + PLANE),     v_r);  // residuals
    __stcs((float4*)(out + off + 2 * PLANE), v_r);  // quantized residuals
    __stcs((float4*)(out + off + 3 * PLANE), v_m);  // mapped indices
    __stcs((float4*)(out + off + 4 * PLANE), v_c);  // sample representatives
    __stcs((float4*)(out + off + 5 * PLANE), v_c);  // reconstructed
}

extern "C" void kernel_launch(void* const* d_in, const int* in_sizes, int n_in,
                              void* d_out, int out_size)
{
    const float* img = (const float*)d_in[0];
    float* out = (float*)d_out;
    ccsds123_kernel<<<ZB * (YB / 2), 256>>>(img, out);
}

// round 11
// speedup vs baseline: 1.0581x; 1.0013x over previous
#include <cuda_runtime.h>

// CCSDS-123 lossless predictor, [Z=224, Y=512, X=512].
// 4 rows per 512-thread block (flat, one barrier), streaming stores.
// 8 KB contiguous per output plane per block for DRAM burst locality.
// (Re-run of R10: prior bench failed in harness allocation, kernel never executed.)

#define ZB 224
#define YB 512
#define XB 512

static constexpr size_t PLANE = (size_t)ZB * YB * XB;   // 58,720,256

__global__ __launch_bounds__(512, 4) void ccsds123_kernel(
    const float* __restrict__ img, float* __restrict__ out)
{
    const int b   = blockIdx.x;          // 224 * 128 blocks
    const int z   = b >> 7;              // / 128
    const int y0  = (b & 127) << 2;      // row quad
    const int tid = threadIdx.x;

    __shared__ float SC[4 * XB];   // center rows y0..y0+3
    __shared__ float SN[XB];       // north row  y0-1
    __shared__ float SP[4 * XB];   // prev band rows y0..y0+3

    const float* base  = img + ((size_t)z * YB + y0) * XB;
    const float* pbase = base - (size_t)YB * XB;     // valid iff z > 0

    // Stage: 512 float4s cover the four center rows / four prev-band rows.
    ((float4*)SC)[tid] = ((const float4*)base)[tid];
    if (z > 0) {
        const float* p = (const float*)((const float4*)pbase + tid);
        float4 pv;
        pv.x = __ldcs(p + 0);
        pv.y = __ldcs(p + 1);
        pv.z = __ldcs(p + 2);
        pv.w = __ldcs(p + 3);
        ((float4*)SP)[tid] = pv;
    } else {
        ((float4*)SP)[tid] = make_float4(0.f, 0.f, 0.f, 0.f);
    }
    if (tid < 128)
        ((float4*)SN)[tid] = (y0 > 0) ? ((const float4*)(base - XB))[tid]
                                      : make_float4(0.f, 0.f, 0.f, 0.f);
    __syncthreads();

    const int q  = tid >> 7;                 // which of the four rows
    const int t  = tid & 127;
    const int x0 = t * 4;
    const int y  = y0 + q;

    const float* sc = SC + q * XB;                     // center s(z, y, :)
    const float* sn = q ? (SC + (q - 1) * XB) : SN;    // north  s(z, y-1, :)
    const float* sp = SP + q * XB;                     // prev   s(z-1, y, :)

    float pr[4], rs[4], mp[4], rc[4];

#pragma unroll
    for (int i = 0; i < 4; ++i) {
        const int x = x0 + i;
        const float Cv  = sc[x];
        const float Wv  = (x > 0)      ? sc[x - 1] : 0.f;
        const float Nv  = sn[x];
        const float NWv = (x > 0)      ? sn[x - 1] : 0.f;
        const float NEv = (x < XB - 1) ? sn[x + 1] : 0.f;

        // neighbor-oriented local sum with edge cases
        float sigma;
        if (y == 0)           sigma = (x == 0) ? 0.f : 4.f * Wv;   // top row
        else if (x == 0)      sigma = 2.f * (Nv + NEv);            // left col
        else if (x == XB - 1) sigma = Wv + NWv + 2.f * Nv;         // right col
        else                  sigma = Wv + NWv + Nv + NEv;         // interior

        const float spred = sigma * 0.25f;
        const float pb    = sp[x];

        float p = (z == 0) ? spred : 0.5f * (spred + pb);
        if (y == 0 && x == 0) p = (z == 0) ? 0.f : pb;             // origin

        const float r = Cv - p;                    // residual (== quantized)
        const float qv = rintf(r);                 // half-to-even, matches jnp.round
        const float m = (qv >= 0.f) ? (2.f * qv) : (-2.f * qv - 1.f); // zigzag
        const float rec = fminf(fmaxf(p + r, -32768.f), 32767.f);  // clip

        pr[i] = p; rs[i] = r; mp[i] = m; rc[i] = rec;
    }

    const size_t off = ((size_t)z * YB + y) * XB + (size_t)x0;
    const float4 v_p = make_float4(pr[0], pr[1], pr[2], pr[3]);
    const float4 v_r = make_float4(rs[0], rs[1], rs[2], rs[3]);
    const float4 v_m = make_float4(mp[0], mp[1], mp[2], mp[3]);
    const float4 v_c = make_float4(rc[0], rc[1], rc[2], rc[3]);

    __stcs((float4*)(out + off),             v_p);  // predictions
    __stcs((float4*)(out + off + PLANE),     v_r);  // residuals
    __stcs((float4*)(out + off + 2 * PLANE), v_r);  // quantized residuals
    __stcs((float4*)(out + off + 3 * PLANE), v_m);  // mapped indices
    __stcs((float4*)(out + off + 4 * PLANE), v_c);  // sample representatives
    __stcs((float4*)(out + off + 5 * PLANE), v_c);  // reconstructed
}

extern "C" void kernel_launch(void* const* d_in, const int* in_sizes, int n_in,
                              void* d_out, int out_size)
{
    const float* img = (const float*)d_in[0];
    float* out = (float*)d_out;
    ccsds123_kernel<<<ZB * (YB / 4), 512>>>(img, out);
}